// round 16
// baseline (speedup 1.0000x reference)
#include <cuda_runtime.h>
#include <cuda_bf16.h>
#include <cstdint>
#include <cstddef>

// CCLayer via HMMA bf16. TILE=64, 256 threads, 4 CTAs/SM.
// R12/R15 structure + cross-tile pipelining: W/SARR de-aliased from A so the
// trailing barrier is gone — GEMM2(t) overlaps phase-1(t+1) global loads.
//   D1[j,p] = Z_tile^T @ U ; w = (alpha - D1).*Pi ; s = colsum(Pi)
//   D2[j,d] = w @ U^T ; out[0:256] = z*s + D2 ; out[256:288] = Pi
#define DD 256
#define PP 32
#define TILE 64
#define THREADS 256

#define U1_STR 528           // U1[p][d] bf16 rows
#define D1_STR 132           // 33 words, gcd(33,32)=1 -> conflict-free epi reads
#define D1_KH  8448          // 64*132
#define W_STR  84            // W[j][p] bf16 rows

// ---- persistent smem (bytes) ----
#define OFF_A      0         // 256 rows x 128B (64 j bf16), XOR-swizzled  (32KB)
#define OFF_U1H    32768     // 32*528 = 16896
#define OFF_ALPHA  49664     // 32 f32
#define OFF_SPART  49792     // 4*64 f32 = 1024
#define OFF_W      50816     // 64*84 = 5376 (OWN region — enables pipelining)
#define OFF_SARR   56192     // 64 f32 (final s)
#define SMEM_BYTES 56448

// ---- alias inside A region (A dead after GEMM1) ----
#define OFF_D1     0         // 2*8448 = 16896 <= 32768

#define MMA_BF16(d, a0, a1, a2, a3, b0, b1)                                  \
    asm volatile(                                                            \
        "mma.sync.aligned.m16n8k16.row.col.f32.bf16.bf16.f32 "               \
        "{%0,%1,%2,%3}, {%4,%5,%6,%7}, {%8,%9}, {%0,%1,%2,%3};"              \
        : "+f"(d[0]), "+f"(d[1]), "+f"(d[2]), "+f"(d[3])                     \
        : "r"(a0), "r"(a1), "r"(a2), "r"(a3), "r"(b0), "r"(b1))

#define LDSM_T4(r0, r1, r2, r3, addr)                                        \
    asm volatile(                                                            \
        "ldmatrix.sync.aligned.m8n8.x4.trans.shared.b16 {%0,%1,%2,%3}, [%4];"\
        : "=r"(r0), "=r"(r1), "=r"(r2), "=r"(r3) : "r"(addr))

#define LDS32(r, addr) \
    asm volatile("ld.shared.b32 %0, [%1];" : "=r"(r) : "r"(addr))
#define LDSF(r, addr) \
    asm volatile("ld.shared.f32 %0, [%1];" : "=f"(r) : "r"(addr))
#define STS32(addr, v) \
    asm volatile("st.shared.b32 [%0], %1;" :: "r"(addr), "r"(v) : "memory")
#define STS64(addr, v0, v1) \
    asm volatile("st.shared.v2.u32 [%0], {%1,%2};" :: "r"(addr), "r"(v0), "r"(v1) : "memory")
#define STSF(addr, v) \
    asm volatile("st.shared.f32 [%0], %1;" :: "r"(addr), "f"(v) : "memory")

__device__ __forceinline__ uint32_t pack_bf2(float a, float b) {
    return (uint32_t)__bfloat16_as_ushort(__float2bfloat16_rn(a)) |
           ((uint32_t)__bfloat16_as_ushort(__float2bfloat16_rn(b)) << 16);
}

__global__ __launch_bounds__(THREADS, 4)
void cclayer_mma9(const float* __restrict__ ZPi,
                  const float* __restrict__ U,
                  const float* __restrict__ alpha,
                  float* __restrict__ out,
                  int N, int ntiles) {
    extern __shared__ __align__(128) char smem[];
    uint32_t sbase;
    asm("{ .reg .u64 t; cvta.to.shared.u64 t, %1; cvt.u32.u64 %0, t; }"
        : "=r"(sbase) : "l"(smem));

    const int tid = threadIdx.x;
    const int warp = tid >> 5;
    const int lane = tid & 31;
    const size_t sN = (size_t)N;

    // ---- persistent: U1[p][d] bf16, alpha ----
    for (int i = tid; i < DD * PP; i += THREADS) {
        const int d = i >> 5, p = i & 31;
        *(uint16_t*)(smem + OFF_U1H + p * U1_STR + d * 2) =
            __bfloat16_as_ushort(__float2bfloat16_rn(U[i]));
    }
    if (tid < PP) ((float*)(smem + OFF_ALPHA))[tid] = alpha[tid];
    __syncthreads();

    const float* __restrict__ sAlpha = (const float*)(smem + OFF_ALPHA);
    float* __restrict__ sPart = (float*)(smem + OFF_SPART);

    // GEMM1 decode: warp = jh(4) + 4*kh(2)
    const int jh = warp & 3;
    const int kh = warp >> 2;
    const int krow_l = (lane & 7) + ((lane >> 4) & 1) * 8;
    const int jcolb = jh * 32 + ((lane >> 3) & 1) * 16;
    const uint32_t b1off = (uint32_t)((lane >> 2) * U1_STR + (lane & 3) * 4);
    // GEMM2 decode: warp = jblk(4) + 4*dh(2)
    const int jblk = (warp & 3) * 16;
    const int dh = warp >> 2;
    const uint32_t wOffA = (uint32_t)((jblk + (lane >> 2)) * W_STR + (lane & 3) * 4);
    const int p_l = (lane & 7) + ((lane >> 3) & 1) * 8;
    const int dcol_l = ((lane >> 4) & 1) * 8;
    const int j1 = jblk + (lane >> 2);
    // epi1 mapping: 4 p-groups x 64 j
    const int jj = tid & 63;
    const int pg = tid >> 6;             // 0..3, 8 p's each
    const int p0g = pg * 8;

    for (int t = blockIdx.x; t < ntiles; t += gridDim.x) {
        const int col0 = t * TILE;

        // ===== phase 1: Z tile -> A bf16 (LDG.128 + STS.64, swizzled) =====
        // (no barrier between previous tile's GEMM2 and these loads)
#pragma unroll 4
        for (int i = 0; i < 16; i++) {
            const int d = warp * 32 + i * 2 + (lane >> 4);
            const int jc = (lane & 15) * 4;
            const float4 v = *(const float4*)(ZPi + (size_t)d * sN + col0 + jc);
            const uint32_t off = (uint32_t)(d * 128 + jc * 2) ^ (uint32_t)((d & 7) << 4);
            STS64(sbase + OFF_A + off, pack_bf2(v.x, v.y), pack_bf2(v.z, v.w));
        }

        // ---- early Pi: regs + pass-through + partial s ----
        float piR[8];
        {
            float sacc = 0.f;
            const size_t c = (size_t)col0 + jj;
#pragma unroll
            for (int i = 0; i < 8; i++) {
                const size_t off = (size_t)(DD + p0g + i) * sN + c;
                piR[i] = ZPi[off];
                out[off] = piR[i];
                sacc += piR[i];
            }
            sPart[pg * 64 + jj] = sacc;
        }
        __syncthreads();                       // sync 1

        // ===== GEMM1: D1[j,p] partials, k-split 2 =====
        float d1[4][4];
#pragma unroll
        for (int nt = 0; nt < 4; nt++)
#pragma unroll
            for (int q = 0; q < 4; q++) d1[nt][q] = 0.f;

#pragma unroll
        for (int ks = 0; ks < 8; ks++) {
            const int dbase = kh * 128 + ks * 16;
            const int d_l = dbase + krow_l;
            const uint32_t asw = (uint32_t)(d_l * 128 + jcolb) ^ (uint32_t)((d_l & 7) << 4);
            uint32_t a0, a1, a2, a3;
            LDSM_T4(a0, a1, a2, a3, sbase + OFF_A + asw);
            const uint32_t bb = sbase + OFF_U1H + b1off + dbase * 2;
#pragma unroll
            for (int nt = 0; nt < 4; nt++) {
                uint32_t b0, b1;
                LDS32(b0, bb + nt * 8 * U1_STR);
                LDS32(b1, bb + nt * 8 * U1_STR + 16);
                MMA_BF16(d1[nt], a0, a1, a2, a3, b0, b1);
            }
        }
        __syncthreads();                       // sync 2 (A reads done)

        // ---- store D1 partials [kh][j][p] (into dead A region) ----
        {
            const uint32_t base = sbase + OFF_D1 + kh * D1_KH;
            const int jr = jh * 16 + (lane >> 2);
#pragma unroll
            for (int nt = 0; nt < 4; nt++) {
                const int p = nt * 8 + 2 * (lane & 3);
                const uint32_t a0 = base + jr * D1_STR + p * 4;
                const uint32_t a1 = base + (jr + 8) * D1_STR + p * 4;
                STSF(a0, d1[nt][0]);
                STSF(a0 + 4, d1[nt][1]);
                STSF(a1, d1[nt][2]);
                STSF(a1 + 4, d1[nt][3]);
            }
        }
        __syncthreads();                       // sync 3

        // ===== epilogue 1: w from D1 + reg Pi; final s -> SARR =====
        {
            const uint32_t db = sbase + OFF_D1 + jj * D1_STR;
            float wv[8];
#pragma unroll
            for (int i = 0; i < 8; i++) {
                const int p = p0g + i;
                float x0, x1;
                LDSF(x0, db + p * 4);
                LDSF(x1, db + D1_KH + p * 4);
                wv[i] = (sAlpha[p] - (x0 + x1)) * piR[i];
            }
            const uint32_t wa = sbase + OFF_W + (uint32_t)(jj * W_STR + p0g * 2);
#pragma unroll
            for (int i = 0; i < 4; i++)
                STS32(wa + i * 4, pack_bf2(wv[2 * i], wv[2 * i + 1]));
            if (pg == 0) {
                ((float*)(smem + OFF_SARR))[jj] =
                    sPart[jj] + sPart[64 + jj] + sPart[128 + jj] + sPart[192 + jj];
            }
        }
        __syncthreads();                       // sync 4 (W/SARR ready; D1 dead)

        // ===== GEMM2 + fused epilogue 2 (flows into next tile, no barrier) =====
        float s1, s2;
        LDSF(s1, sbase + OFF_SARR + (uint32_t)(j1 * 4));
        LDSF(s2, sbase + OFF_SARR + (uint32_t)((j1 + 8) * 4));

        // a-frags (w) for both k16 steps, loaded once
        uint32_t aw[2][4];
#pragma unroll
        for (int ks = 0; ks < 2; ks++) {
            const uint32_t wh = sbase + OFF_W + wOffA + ks * 32;
            LDS32(aw[ks][0], wh);
            LDS32(aw[ks][1], wh + 8 * W_STR);
            LDS32(aw[ks][2], wh + 16);
            LDS32(aw[ks][3], wh + 8 * W_STR + 16);
        }

        const size_t c1 = (size_t)col0 + j1;
#pragma unroll 1
        for (int h = 0; h < 4; h++) {        // four 32-d slices of this half
            // preload epilogue Z values before the MMAs
            float zr[4][4];
#pragma unroll
            for (int nt = 0; nt < 4; nt++) {
                const int d0 = dh * 128 + h * 32 + nt * 8 + 2 * (lane & 3);
                const size_t o00 = (size_t)d0 * sN + c1;
                const size_t o01 = (size_t)(d0 + 1) * sN + c1;
                zr[nt][0] = ZPi[o00];
                zr[nt][1] = ZPi[o01];
                zr[nt][2] = ZPi[o00 + 8];
                zr[nt][3] = ZPi[o01 + 8];
            }

            float d2[4][4];
#pragma unroll
            for (int nt = 0; nt < 4; nt++)
#pragma unroll
                for (int q = 0; q < 4; q++) d2[nt][q] = 0.f;

#pragma unroll
            for (int ks = 0; ks < 2; ks++) {
#pragma unroll
                for (int ntp = 0; ntp < 2; ntp++) {
                    const int d0p = dh * 128 + h * 32 + ntp * 16;
                    const uint32_t la = (uint32_t)((ks * 16 + p_l) * U1_STR +
                                                   (d0p + dcol_l) * 2);
                    uint32_t b0, b1, b2, b3;
                    LDSM_T4(b0, b1, b2, b3, sbase + OFF_U1H + la);
                    MMA_BF16(d2[2 * ntp], aw[ks][0], aw[ks][1], aw[ks][2], aw[ks][3], b0, b1);
                    MMA_BF16(d2[2 * ntp + 1], aw[ks][0], aw[ks][1], aw[ks][2], aw[ks][3], b2, b3);
                }
            }

            // fused epilogue 2: out = z*s + D2 (32B-sector coalesced)
#pragma unroll
            for (int nt = 0; nt < 4; nt++) {
                const int d0 = dh * 128 + h * 32 + nt * 8 + 2 * (lane & 3);
                const size_t o00 = (size_t)d0 * sN + c1;
                const size_t o01 = (size_t)(d0 + 1) * sN + c1;
                out[o00] = fmaf(zr[nt][0], s1, d2[nt][0]);
                out[o01] = fmaf(zr[nt][1], s1, d2[nt][1]);
                out[o00 + 8] = fmaf(zr[nt][2], s2, d2[nt][2]);
                out[o01 + 8] = fmaf(zr[nt][3], s2, d2[nt][3]);
            }
        }
        // NO trailing barrier: warps run ahead into next tile's phase 1.
    }
}

extern "C" void kernel_launch(void* const* d_in, const int* in_sizes, int n_in,
                              void* d_out, int out_size) {
    const float* ZPi   = (const float*)d_in[0];
    const float* U     = (const float*)d_in[1];
    const float* alpha = (const float*)d_in[2];
    float* out = (float*)d_out;

    const int N = in_sizes[0] / (DD + PP);
    const int ntiles = N / TILE;

    static int nsm = 0;
    if (nsm == 0) {
        cudaDeviceGetAttribute(&nsm, cudaDevAttrMultiProcessorCount, 0);
        cudaFuncSetAttribute(cclayer_mma9, cudaFuncAttributeMaxDynamicSharedMemorySize,
                             SMEM_BYTES);
    }
    int grid = 4 * nsm;
    if (grid > ntiles) grid = ntiles;
    cclayer_mma9<<<grid, THREADS, SMEM_BYTES>>>(ZPi, U, alpha, out, N, ntiles);
}

// round 17
// speedup vs baseline: 1.1726x; 1.1726x over previous
#include <cuda_runtime.h>
#include <cuda_bf16.h>
#include <cstdint>
#include <cstddef>

// CCLayer via HMMA bf16. TILE=128, 256 threads, 2 CTAs/SM, 2 barriers/tile.
//   D1[j,p] = Z_tile^T @ U  (full-K per warp -> D1 stays in registers)
//   w = (alpha - D1).*Pi ; s = colsum(Pi)
//   D2[j,d] = w @ U^T ; out[0:256] = z*s + D2 ; out[256:288] = Pi
#define DD 256
#define PP 32
#define TILE 128
#define THREADS 256

#define U1_STR 528           // U1[p][d] bf16 rows (132 words; 132%32=4 -> conflict-free)
#define W_STR  80            // W[j][p] bf16 rows (20 words; 20*jr mod 32 gap-4 -> exact)

// ---- smem (bytes) ----
#define OFF_A      0         // 256 rows x 256B (128 j bf16), XOR-swizzled (64KB)
#define OFF_U1H    65536     // 32*528 = 16896
#define OFF_ALPHA  82432     // 32 f32
#define OFF_SPART  82560     // 2*128 f32 = 1024
#define OFF_W      83584     // 128*80 = 10240
#define OFF_SARR   93824     // 128 f32
#define SMEM_BYTES 94336

#define MMA_BF16(d, a0, a1, a2, a3, b0, b1)                                  \
    asm volatile(                                                            \
        "mma.sync.aligned.m16n8k16.row.col.f32.bf16.bf16.f32 "               \
        "{%0,%1,%2,%3}, {%4,%5,%6,%7}, {%8,%9}, {%0,%1,%2,%3};"              \
        : "+f"(d[0]), "+f"(d[1]), "+f"(d[2]), "+f"(d[3])                     \
        : "r"(a0), "r"(a1), "r"(a2), "r"(a3), "r"(b0), "r"(b1))

#define LDSM_T4(r0, r1, r2, r3, addr)                                        \
    asm volatile(                                                            \
        "ldmatrix.sync.aligned.m8n8.x4.trans.shared.b16 {%0,%1,%2,%3}, [%4];"\
        : "=r"(r0), "=r"(r1), "=r"(r2), "=r"(r3) : "r"(addr))

#define LDS32(r, addr) \
    asm volatile("ld.shared.b32 %0, [%1];" : "=r"(r) : "r"(addr))
#define LDSF(r, addr) \
    asm volatile("ld.shared.f32 %0, [%1];" : "=f"(r) : "r"(addr))
#define STS32(addr, v) \
    asm volatile("st.shared.b32 [%0], %1;" :: "r"(addr), "r"(v) : "memory")
#define STS64(addr, v0, v1) \
    asm volatile("st.shared.v2.u32 [%0], {%1,%2};" :: "r"(addr), "r"(v0), "r"(v1) : "memory")
#define STSF(addr, v) \
    asm volatile("st.shared.f32 [%0], %1;" :: "r"(addr), "f"(v) : "memory")

__device__ __forceinline__ uint32_t pack_bf2(float a, float b) {
    return (uint32_t)__bfloat16_as_ushort(__float2bfloat16_rn(a)) |
           ((uint32_t)__bfloat16_as_ushort(__float2bfloat16_rn(b)) << 16);
}

__global__ __launch_bounds__(THREADS, 2)
void cclayer_mma10(const float* __restrict__ ZPi,
                   const float* __restrict__ U,
                   const float* __restrict__ alpha,
                   float* __restrict__ out,
                   int N, int ntiles) {
    extern __shared__ __align__(128) char smem[];
    uint32_t sbase;
    asm("{ .reg .u64 t; cvta.to.shared.u64 t, %1; cvt.u32.u64 %0, t; }"
        : "=r"(sbase) : "l"(smem));

    const int tid = threadIdx.x;
    const int warp = tid >> 5;
    const int lane = tid & 31;
    const size_t sN = (size_t)N;

    // ---- persistent: U1[p][d] bf16, alpha ----
    for (int i = tid; i < DD * PP; i += THREADS) {
        const int d = i >> 5, p = i & 31;
        *(uint16_t*)(smem + OFF_U1H + p * U1_STR + d * 2) =
            __bfloat16_as_ushort(__float2bfloat16_rn(U[i]));
    }
    if (tid < PP) ((float*)(smem + OFF_ALPHA))[tid] = alpha[tid];
    __syncthreads();

    const float* __restrict__ sAlpha = (const float*)(smem + OFF_ALPHA);
    float* __restrict__ sPart = (float*)(smem + OFF_SPART);

    // lane decode (shared by both GEMMs)
    const int krow_l = (lane & 7) + ((lane >> 4) & 1) * 8;   // A-frag k-row
    const int p_l = (lane & 7) + ((lane >> 3) & 1) * 8;      // GEMM2 B k-row (p)
    const int dcol_l = ((lane >> 4) & 1) * 8;                // GEMM2 B col-block
    // GEMM1: warp owns j-block warp*16, full K
    const int jblk = warp * 16;
    const int jcolb = jblk * 2 + ((lane >> 3) & 1) * 16;
    const uint32_t b1off = (uint32_t)((lane >> 2) * U1_STR + (lane & 3) * 4);
    const int jr = jblk + (lane >> 2);          // fragment row (j)
    // GEMM2: same j-block; a-frags from W
    const uint32_t wOffA = (uint32_t)(jr * W_STR + (lane & 3) * 4);
    // Pi pass mapping: 2 p-groups x 128 j
    const int jj = tid & 127;
    const int pgr = tid >> 7;                   // 0..1, 16 p's each

    for (int t = blockIdx.x; t < ntiles; t += gridDim.x) {
        const int col0 = t * TILE;

        // ===== phase 1: Z tile -> A bf16 (LDG.128 + STS.64, swizzled) =====
        // (no barrier between prev tile's GEMM2 and these loads)
#pragma unroll 8
        for (int i = 0; i < 32; i++) {
            const int d = warp * 32 + i;
            const int jc = lane * 4;
            const float4 v = *(const float4*)(ZPi + (size_t)d * sN + col0 + jc);
            const uint32_t off = (uint32_t)(d * 256 + jc * 2) ^ (uint32_t)((d & 7) << 4);
            STS64(sbase + OFF_A + off, pack_bf2(v.x, v.y), pack_bf2(v.z, v.w));
        }
        // ---- Pi pass-through + partial s ----
        {
            float sacc = 0.f;
            const size_t c = (size_t)col0 + jj;
#pragma unroll
            for (int i = 0; i < 16; i++) {
                const size_t off = (size_t)(DD + pgr * 16 + i) * sN + c;
                const float v = ZPi[off];
                out[off] = v;
                sacc += v;
            }
            sPart[pgr * 128 + jj] = sacc;
        }
        __syncthreads();                        // sync 1: A + sPart ready

        // ===== GEMM1: D1[j,p], full K=256, register-resident =====
        float d1[4][4];
#pragma unroll
        for (int nt = 0; nt < 4; nt++)
#pragma unroll
            for (int q = 0; q < 4; q++) d1[nt][q] = 0.f;

#pragma unroll 4
        for (int ks = 0; ks < 16; ks++) {
            const int d_l = ks * 16 + krow_l;
            const uint32_t asw = (uint32_t)(d_l * 256 + jcolb) ^ (uint32_t)((d_l & 7) << 4);
            uint32_t a0, a1, a2, a3;
            LDSM_T4(a0, a1, a2, a3, sbase + OFF_A + asw);
            const uint32_t bb = sbase + OFF_U1H + b1off + ks * 32;
#pragma unroll
            for (int nt = 0; nt < 4; nt++) {
                uint32_t b0, b1;
                LDS32(b0, bb + nt * 8 * U1_STR);
                LDS32(b1, bb + nt * 8 * U1_STR + 16);
                MMA_BF16(d1[nt], a0, a1, a2, a3, b0, b1);
            }
        }

        // ===== epilogue 1 (in-register D1): w -> W; final s -> SARR =====
        if (tid < 128)
            ((float*)(smem + OFF_SARR))[tid] = sPart[tid] + sPart[128 + tid];
        {
            const size_t c0 = (size_t)col0 + jr;
#pragma unroll
            for (int nt = 0; nt < 4; nt++) {
                const int p0 = nt * 8 + 2 * (lane & 3);
                const float a0 = sAlpha[p0], a1 = sAlpha[p0 + 1];
                const float pi00 = ZPi[(size_t)(DD + p0) * sN + c0];
                const float pi10 = ZPi[(size_t)(DD + p0 + 1) * sN + c0];
                const float pi01 = ZPi[(size_t)(DD + p0) * sN + c0 + 8];
                const float pi11 = ZPi[(size_t)(DD + p0 + 1) * sN + c0 + 8];
                const float w0 = (a0 - d1[nt][0]) * pi00;
                const float w1 = (a1 - d1[nt][1]) * pi10;
                const float w2 = (a0 - d1[nt][2]) * pi01;
                const float w3 = (a1 - d1[nt][3]) * pi11;
                const uint32_t wa = sbase + OFF_W + (uint32_t)(jr * W_STR + p0 * 2);
                STS32(wa, pack_bf2(w0, w1));
                STS32(wa + 8 * W_STR, pack_bf2(w2, w3));
            }
        }
        __syncthreads();                        // sync 2: W + SARR ready

        // ===== GEMM2 + fused epilogue (flows into next tile, no barrier) =====
        float s1, s2;
        LDSF(s1, sbase + OFF_SARR + (uint32_t)(jr * 4));
        LDSF(s2, sbase + OFF_SARR + (uint32_t)((jr + 8) * 4));

        uint32_t aw[2][4];
#pragma unroll
        for (int ks = 0; ks < 2; ks++) {
            const uint32_t wh = sbase + OFF_W + wOffA + ks * 32;
            LDS32(aw[ks][0], wh);
            LDS32(aw[ks][1], wh + 8 * W_STR);
            LDS32(aw[ks][2], wh + 16);
            LDS32(aw[ks][3], wh + 8 * W_STR + 16);
        }

        const size_t c1 = (size_t)col0 + jr;
#pragma unroll 1
        for (int h = 0; h < 8; h++) {           // eight 32-d slices
            // batched preload of epilogue Z values before the MMAs
            float zr[4][4];
#pragma unroll
            for (int nt = 0; nt < 4; nt++) {
                const int d0 = h * 32 + nt * 8 + 2 * (lane & 3);
                const size_t o00 = (size_t)d0 * sN + c1;
                const size_t o01 = (size_t)(d0 + 1) * sN + c1;
                zr[nt][0] = ZPi[o00];
                zr[nt][1] = ZPi[o01];
                zr[nt][2] = ZPi[o00 + 8];
                zr[nt][3] = ZPi[o01 + 8];
            }

            float d2[4][4];
#pragma unroll
            for (int nt = 0; nt < 4; nt++)
#pragma unroll
                for (int q = 0; q < 4; q++) d2[nt][q] = 0.f;

#pragma unroll
            for (int ks = 0; ks < 2; ks++) {
#pragma unroll
                for (int ntp = 0; ntp < 2; ntp++) {
                    const int d0p = h * 32 + ntp * 16;
                    const uint32_t la = (uint32_t)(OFF_U1H + (ks * 16 + p_l) * U1_STR +
                                                   (d0p + dcol_l) * 2);
                    uint32_t b0, b1, b2, b3;
                    LDSM_T4(b0, b1, b2, b3, sbase + la);
                    MMA_BF16(d2[2 * ntp], aw[ks][0], aw[ks][1], aw[ks][2], aw[ks][3], b0, b1);
                    MMA_BF16(d2[2 * ntp + 1], aw[ks][0], aw[ks][1], aw[ks][2], aw[ks][3], b2, b3);
                }
            }

            // fused epilogue 2: out = z*s + D2 (32B-sector coalesced)
#pragma unroll
            for (int nt = 0; nt < 4; nt++) {
                const int d0 = h * 32 + nt * 8 + 2 * (lane & 3);
                const size_t o00 = (size_t)d0 * sN + c1;
                const size_t o01 = (size_t)(d0 + 1) * sN + c1;
                out[o00] = fmaf(zr[nt][0], s1, d2[nt][0]);
                out[o01] = fmaf(zr[nt][1], s1, d2[nt][1]);
                out[o00 + 8] = fmaf(zr[nt][2], s2, d2[nt][2]);
                out[o01 + 8] = fmaf(zr[nt][3], s2, d2[nt][3]);
            }
        }
        // NO trailing barrier: warps run ahead into next tile's phase 1.
    }
}

extern "C" void kernel_launch(void* const* d_in, const int* in_sizes, int n_in,
                              void* d_out, int out_size) {
    const float* ZPi   = (const float*)d_in[0];
    const float* U     = (const float*)d_in[1];
    const float* alpha = (const float*)d_in[2];
    float* out = (float*)d_out;

    const int N = in_sizes[0] / (DD + PP);
    const int ntiles = N / TILE;

    static int nsm = 0;
    if (nsm == 0) {
        cudaDeviceGetAttribute(&nsm, cudaDevAttrMultiProcessorCount, 0);
        cudaFuncSetAttribute(cclayer_mma10, cudaFuncAttributeMaxDynamicSharedMemorySize,
                             SMEM_BYTES);
    }
    int grid = 2 * nsm;
    if (grid > ntiles) grid = ntiles;
    cclayer_mma10<<<grid, THREADS, SMEM_BYTES>>>(ZPi, U, alpha, out, N, ntiles);
}